// round 7
// baseline (speedup 1.0000x reference)
#include <cuda_runtime.h>
#include <cstdint>
#include <math.h>

// ---------------- problem constants ----------------
#define NQ     4096
#define NM     100000
#define D      128
#define NCH    37
#define CHUNK  2703          // ceil(NM / NCH)
#define QT     128           // queries per CTA (block M)
#define NT     128           // memory rows per tile (block N)
#define KC     8             // candidates kept per (query, chunk)

#define A_BYTES   (QT * D)              // s8: 16384
#define B_BYTES   (NT * D)              // 16384
#define NBUF      3
#define SMEM_DYN  (A_BYTES + NBUF * B_BYTES + 1024)   // ~66KB

// ---------------- device scratch ----------------
__device__ float     g_qn[NQ * D];        // normalized queries (fp32)
__device__ uint32_t  g_qs8[NQ * 32];      // normalized queries (s8 x127, 4/word)
__device__ uint32_t  g_ms8[NM * 32];      // normalized memory (s8 x127)
__device__ float     g_invm[NM];          // 1/||m||
__device__ int       g_ci[NQ * NCH * KC];
__device__ int       g_dummy;

// ---------------- PTX helpers (family-generic, sm_80-era) ----------------
__device__ __forceinline__ uint32_t s2u(const void* p) {
    uint32_t a;
    asm("{ .reg .u64 t; cvta.to.shared.u64 t, %1; cvt.u32.u64 %0, t; }"
        : "=r"(a) : "l"(p));
    return a;
}

__device__ __forceinline__ void cp16(uint32_t dst, const void* src) {
    asm volatile("cp.async.cg.shared.global [%0], [%1], 16;" :: "r"(dst), "l"(src));
}
#define CP_COMMIT() asm volatile("cp.async.commit_group;" ::: "memory")
#define CP_WAIT0()  asm volatile("cp.async.wait_group 0;" ::: "memory")
#define CP_WAIT1()  asm volatile("cp.async.wait_group 1;" ::: "memory")

__device__ __forceinline__ void ldsm_x4(uint32_t addr, uint32_t& r0, uint32_t& r1,
                                        uint32_t& r2, uint32_t& r3) {
    asm volatile("ldmatrix.sync.aligned.m8n8.x4.shared.b16 {%0,%1,%2,%3}, [%4];"
        : "=r"(r0), "=r"(r1), "=r"(r2), "=r"(r3) : "r"(addr));
}

// int8 IMMA: m16n8k32, s32 accumulate
__device__ __forceinline__ void mma16832_s8(int* d, const uint32_t* a, const uint32_t* b) {
    asm volatile("mma.sync.aligned.m16n8k32.row.col.s32.s8.s8.s32 "
        "{%0,%1,%2,%3}, {%4,%5,%6,%7}, {%8,%9}, {%0,%1,%2,%3};"
        : "+r"(d[0]), "+r"(d[1]), "+r"(d[2]), "+r"(d[3])
        : "r"(a[0]), "r"(a[1]), "r"(a[2]), "r"(a[3]), "r"(b[0]), "r"(b[1]));
}

// swizzled byte offset: rows of 128 bytes, 16B chunks XOR-permuted per row
__device__ __forceinline__ uint32_t sw_off(int row, int c16) {
    return (uint32_t)row * 128u + (uint32_t)((c16 ^ (row & 7)) * 16);
}

// ---------------- top-k inserts ----------------
__device__ __forceinline__ void ins_tb3(float s, int gi,
    float& v0, int& i0, float& v1, int& i1, float& v2, int& i2) {
    bool b2 = (s > v2) || (s == v2 && gi < i2);
    if (!b2) return;
    bool b1 = (s > v1) || (s == v1 && gi < i1);
    if (b1) {
        bool b0 = (s > v0) || (s == v0 && gi < i0);
        if (b0) { v2=v1;i2=i1; v1=v0;i1=i0; v0=s;i0=gi; }
        else    { v2=v1;i2=i1; v1=s;i1=gi; }
    } else      { v2=s; i2=gi; }
}

__device__ __forceinline__ void ins_ti4(int s, int gi,
    int& v0, int& i0, int& v1, int& i1, int& v2, int& i2, int& v3, int& i3) {
    if (!(s > v3)) return;
    if (s > v1) {
        if (s > v0) { v3=v2;i3=i2; v2=v1;i2=i1; v1=v0;i1=i0; v0=s;i0=gi; }
        else        { v3=v2;i3=i2; v2=v1;i2=i1; v1=s;i1=gi; }
    } else {
        if (s > v2) { v3=v2;i3=i2; v2=s;i2=gi; }
        else        { v3=s; i3=gi; }
    }
}

// ---------------- fused prep kernel (normalize q + m, emit s8) ----------------
__global__ void prep_kernel(const float* __restrict__ q, const float* __restrict__ m) {
    int w    = (blockIdx.x * blockDim.x + threadIdx.x) >> 5;
    int lane = threadIdx.x & 31;
    if (w < NQ) {
        float4 v = *(const float4*)(q + (size_t)w * D + lane * 4);
        float ss = v.x*v.x + v.y*v.y + v.z*v.z + v.w*v.w;
        #pragma unroll
        for (int o = 16; o; o >>= 1) ss += __shfl_xor_sync(0xffffffffu, ss, o);
        float inv = 1.0f / fmaxf(sqrtf(ss), 1e-12f);
        float4 r = { v.x*inv, v.y*inv, v.z*inv, v.w*inv };
        *(float4*)(g_qn + (size_t)w * D + lane * 4) = r;
        int a = __float2int_rn(r.x * 127.0f), b = __float2int_rn(r.y * 127.0f);
        int c = __float2int_rn(r.z * 127.0f), d = __float2int_rn(r.w * 127.0f);
        g_qs8[(size_t)w * 32 + lane] =
            (a & 0xff) | ((b & 0xff) << 8) | ((c & 0xff) << 16) | ((d & 0xff) << 24);
    } else if (w < NQ + NM) {
        int row = w - NQ;
        float4 v = *(const float4*)(m + (size_t)row * D + lane * 4);
        float ss = v.x*v.x + v.y*v.y + v.z*v.z + v.w*v.w;
        #pragma unroll
        for (int o = 16; o; o >>= 1) ss += __shfl_xor_sync(0xffffffffu, ss, o);
        float inv = 1.0f / fmaxf(sqrtf(ss), 1e-12f);
        if (lane == 0) g_invm[row] = inv;
        int a = __float2int_rn(v.x * inv * 127.0f), b = __float2int_rn(v.y * inv * 127.0f);
        int c = __float2int_rn(v.z * inv * 127.0f), d = __float2int_rn(v.w * inv * 127.0f);
        g_ms8[(size_t)row * 32 + lane] =
            (a & 0xff) | ((b & 0xff) << 8) | ((c & 0xff) << 16) | ((d & 0xff) << 24);
    }
}

// ---------------- tiny dummy kernels (shift ncu profiled slot) ----------------
__global__ void dummy_kernel(int v) { if (threadIdx.x == 1025) g_dummy = v; }

// ---------------- main INT8 IMMA + top-8 kernel ----------------
// 512 threads = 16 warps (4M x 4N). Block tile 128x128, K=128.
// A fragments hoisted; B triple-buffered, lookahead-1 cp.async pipeline.
__global__ __launch_bounds__(512, 1) void mma_topk_kernel() {
    extern __shared__ __align__(16) uint8_t dyn[];

    int tid  = threadIdx.x;
    int wid  = tid >> 5;
    int lane = tid & 31;
    int wm   = wid & 3;       // warp row: 32 queries
    int wn   = wid >> 2;      // warp col: 32 memory rows (0..3)

    uint32_t raw  = s2u(dyn);
    uint32_t base = (raw + 1023u) & ~1023u;
    uint8_t* dbase = (uint8_t*)dyn + (base - raw);
    uint32_t aSm  = base;
    uint32_t bSm  = base + A_BYTES;   // 3 buffers of B_BYTES

    int qbase  = blockIdx.x * QT;
    int chunk  = blockIdx.y;
    int mstart = chunk * CHUNK;
    int mend   = min(mstart + CHUNK, NM);
    int T      = (mend - mstart + NT - 1) / NT;

    const char* ms8 = (const char*)g_ms8;
    const char* qs8 = (const char*)g_qs8;

    // loader geometry: 128 rows, 4 threads/row, 32B each
    int ldRow  = tid >> 2;
    int ldC16  = (tid & 3) * 2;

    // ---- prologue: A tile + B tile 0 (group 0), B tile 1 (group 1) ----
    #pragma unroll
    for (int j = 0; j < 2; ++j)
        cp16(aSm + sw_off(ldRow, ldC16 + j), qs8 + (size_t)(qbase + ldRow) * 128 + (ldC16 + j) * 16);
    {
        int gr = min(mstart + ldRow, NM - 1);
        #pragma unroll
        for (int j = 0; j < 2; ++j)
            cp16(bSm + sw_off(ldRow, ldC16 + j), ms8 + (size_t)gr * 128 + (ldC16 + j) * 16);
    }
    CP_COMMIT();
    if (T > 1) {
        int gr = min(mstart + NT + ldRow, NM - 1);
        #pragma unroll
        for (int j = 0; j < 2; ++j)
            cp16(bSm + B_BYTES + sw_off(ldRow, ldC16 + j), ms8 + (size_t)gr * 128 + (ldC16 + j) * 16);
        CP_COMMIT();
        CP_WAIT1();
    } else {
        CP_WAIT0();
    }
    __syncthreads();

    // ---- hoist A fragments (constant across all tiles) ----
    int rowA0 = wm * 32 + (lane & 15);
    int hiA   = lane >> 4;
    uint32_t afr[4][2][4];
    #pragma unroll
    for (int kk = 0; kk < 4; ++kk)
        #pragma unroll
        for (int mt = 0; mt < 2; ++mt)
            ldsm_x4(aSm + sw_off(rowA0 + mt * 16, 2 * kk + hiA),
                    afr[kk][mt][0], afr[kk][mt][1], afr[kk][mt][2], afr[kk][mt][3]);

    // per-thread top-4 for 4 row-slots
    int tv0[4], tv1[4], tv2[4], tv3[4];
    int ti0[4], ti1[4], ti2[4], ti3[4];
    #pragma unroll
    for (int r = 0; r < 4; ++r) {
        tv0[r]=tv1[r]=tv2[r]=tv3[r] = -0x7fffffff;
        ti0[r]=ti1[r]=ti2[r]=ti3[r] = 0x7fffffff;
    }

    int grp   = lane >> 3;
    int rowB0 = wn * 32 + (lane & 7) + (grp >> 1) * 8;
    int hiB   = grp & 1;

    for (int t = 0; t < T; ++t) {
        int cur = t % NBUF;
        if (t >= 1 && t + 1 < T) {
            uint32_t bNext = bSm + ((t + 1) % NBUF) * B_BYTES;
            int gr = min(mstart + (t + 1) * NT + ldRow, NM - 1);
            #pragma unroll
            for (int j = 0; j < 2; ++j)
                cp16(bNext + sw_off(ldRow, ldC16 + j), ms8 + (size_t)gr * 128 + (ldC16 + j) * 16);
            CP_COMMIT();
        }
        if (t + 1 < T) CP_WAIT1(); else CP_WAIT0();
        __syncthreads();

        uint32_t bB = bSm + cur * B_BYTES;
        int tb = mstart + t * NT;

        // ---- 128x128x128 block tile, s8 (4 K-steps of 32) ----
        int acc[2][4][4];
        #pragma unroll
        for (int mt = 0; mt < 2; ++mt)
            #pragma unroll
            for (int nt = 0; nt < 4; ++nt)
                #pragma unroll
                for (int e = 0; e < 4; ++e) acc[mt][nt][e] = 0;

        #pragma unroll
        for (int kk = 0; kk < 4; ++kk) {
            uint32_t b[4][2];
            #pragma unroll
            for (int j = 0; j < 2; ++j)
                ldsm_x4(bB + sw_off(rowB0 + j * 16, 2 * kk + hiB),
                        b[2*j][0], b[2*j][1], b[2*j+1][0], b[2*j+1][1]);
            #pragma unroll
            for (int mt = 0; mt < 2; ++mt)
                #pragma unroll
                for (int nt = 0; nt < 4; ++nt)
                    mma16832_s8(acc[mt][nt], afr[kk][mt], b[nt]);
        }

        // ---- streaming top-4 epilogue (int compares) ----
        #pragma unroll
        for (int mt = 0; mt < 2; ++mt)
            #pragma unroll
            for (int h = 0; h < 2; ++h) {
                const int rs = mt * 2 + h;
                #pragma unroll
                for (int nt = 0; nt < 4; ++nt)
                    #pragma unroll
                    for (int c = 0; c < 2; ++c) {
                        int s = acc[mt][nt][h * 2 + c];
                        int gi = tb + wn * 32 + nt * 8 + (lane & 3) * 2 + c;
                        if (gi < mend && s > tv3[rs])
                            ins_ti4(s, gi, tv0[rs],ti0[rs], tv1[rs],ti1[rs],
                                           tv2[rs],ti2[rs], tv3[rs],ti3[rs]);
                    }
            }
    }

    // ---- merge across the 4 lanes sharing each row (xor 1, 2) ----
    #pragma unroll
    for (int off = 1; off <= 2; off <<= 1) {
        #pragma unroll
        for (int rs = 0; rs < 4; ++rs) {
            int ov0 = __shfl_xor_sync(0xffffffffu, tv0[rs], off);
            int oi0 = __shfl_xor_sync(0xffffffffu, ti0[rs], off);
            int ov1 = __shfl_xor_sync(0xffffffffu, tv1[rs], off);
            int oi1 = __shfl_xor_sync(0xffffffffu, ti1[rs], off);
            int ov2 = __shfl_xor_sync(0xffffffffu, tv2[rs], off);
            int oi2 = __shfl_xor_sync(0xffffffffu, ti2[rs], off);
            int ov3 = __shfl_xor_sync(0xffffffffu, tv3[rs], off);
            int oi3 = __shfl_xor_sync(0xffffffffu, ti3[rs], off);
            ins_ti4(ov0, oi0, tv0[rs],ti0[rs], tv1[rs],ti1[rs], tv2[rs],ti2[rs], tv3[rs],ti3[rs]);
            ins_ti4(ov1, oi1, tv0[rs],ti0[rs], tv1[rs],ti1[rs], tv2[rs],ti2[rs], tv3[rs],ti3[rs]);
            ins_ti4(ov2, oi2, tv0[rs],ti0[rs], tv1[rs],ti1[rs], tv2[rs],ti2[rs], tv3[rs],ti3[rs]);
            ins_ti4(ov3, oi3, tv0[rs],ti0[rs], tv1[rs],ti1[rs], tv2[rs],ti2[rs], tv3[rs],ti3[rs]);
        }
    }
    __syncthreads();   // all loads drained; smem reusable

    // ---- cross-warp_n merge via smem: [4 wn][128 rows][4 slots] ----
    int* smv = (int*)dbase;                         // 8 KB
    int* smi = (int*)(dbase + 4 * 128 * 4 * 4);     // 8 KB
    if ((lane & 3) == 0) {
        #pragma unroll
        for (int rs = 0; rs < 4; ++rs) {
            int row = wm * 32 + (rs >> 1) * 16 + (lane >> 2) + (rs & 1) * 8;
            int o = (wn * 128 + row) * 4;
            smv[o+0]=tv0[rs]; smi[o+0]=ti0[rs];
            smv[o+1]=tv1[rs]; smi[o+1]=ti1[rs];
            smv[o+2]=tv2[rs]; smi[o+2]=ti2[rs];
            smv[o+3]=tv3[rs]; smi[o+3]=ti3[rs];
        }
    }
    __syncthreads();
    if (tid < 128) {
        int row = tid;
        int av[16], ai[16];
        #pragma unroll
        for (int seg = 0; seg < 4; ++seg)
            #pragma unroll
            for (int j = 0; j < 4; ++j) {
                av[seg*4+j] = smv[(seg * 128 + row) * 4 + j];
                ai[seg*4+j] = smi[(seg * 128 + row) * 4 + j];
            }
        size_t cb = ((size_t)(qbase + row) * NCH + chunk) * KC;
        #pragma unroll
        for (int s = 0; s < KC; ++s) {
            int best = s;
            for (int j = s + 1; j < 16; ++j)
                if (av[j] > av[best]) best = j;
            int bv = av[best], bi = ai[best];
            av[best] = av[s]; ai[best] = ai[s];
            av[s] = bv; ai[s] = bi;
            g_ci[cb + s] = bi;
        }
    }
}

// ---------------- exact fp32 rescore + final top-3 ----------------
__global__ void rescore_kernel(const float* __restrict__ mem, float* __restrict__ out) {
    __shared__ float sv[8][3];
    __shared__ int   si[8][3];

    int tid   = threadIdx.x;
    int wid   = tid >> 5;
    int lane  = tid & 31;
    int qidx  = blockIdx.x;

    float4 qv = *(const float4*)(g_qn + (size_t)qidx * D + lane * 4);

    float v0 = -2.f, v1 = -2.f, v2 = -2.f;
    int   i0 = 0x7fffffff, i1 = 0x7fffffff, i2 = 0x7fffffff;

    size_t cb = (size_t)qidx * NCH * KC;
    #pragma unroll 1
    for (int j = wid; j < NCH * KC; j += 8) {
        int gi = g_ci[cb + j];
        if ((unsigned)gi >= (unsigned)NM) continue;
        float4 mv = *(const float4*)(mem + (size_t)gi * D + lane * 4);
        float s = qv.x*mv.x + qv.y*mv.y + qv.z*mv.z + qv.w*mv.w;
        #pragma unroll
        for (int o = 16; o; o >>= 1) s += __shfl_xor_sync(0xffffffffu, s, o);
        s *= g_invm[gi];
        ins_tb3(s, gi, v0, i0, v1, i1, v2, i2);
    }
    if (lane == 0) {
        sv[wid][0]=v0; si[wid][0]=i0;
        sv[wid][1]=v1; si[wid][1]=i1;
        sv[wid][2]=v2; si[wid][2]=i2;
    }
    __syncthreads();

    if (tid == 0) {
        float w0 = -2.f, w1 = -2.f, w2 = -2.f;
        int   a0 = 0x7fffffff, a1 = 0x7fffffff, a2 = 0x7fffffff;
        #pragma unroll
        for (int p = 0; p < 8; ++p)
            #pragma unroll
            for (int j = 0; j < 3; ++j)
                ins_tb3(sv[p][j], si[p][j], w0,a0, w1,a1, w2,a2);
        out[(size_t)qidx * 3 + 0] = 1.0f - w0;
        out[(size_t)qidx * 3 + 1] = 1.0f - w1;
        out[(size_t)qidx * 3 + 2] = 1.0f - w2;
        out[(size_t)NQ * 3 + (size_t)qidx * 3 + 0] = (float)a0;
        out[(size_t)NQ * 3 + (size_t)qidx * 3 + 1] = (float)a1;
        out[(size_t)NQ * 3 + (size_t)qidx * 3 + 2] = (float)a2;
    }
}

// ---------------- launch ----------------
// Order puts mma_topk_kernel at global launch index 3 so ncu (-s 5 -c 1,
// observed to land on index 3) profiles the main kernel next round.
extern "C" void kernel_launch(void* const* d_in, const int* in_sizes, int n_in,
                              void* d_out, int out_size) {
    const float* q   = (const float*)d_in[0];
    const float* mem = (const float*)d_in[1];
    float* out = (float*)d_out;

    cudaFuncSetAttribute(mma_topk_kernel,
                         cudaFuncAttributeMaxDynamicSharedMemorySize, SMEM_DYN);

    int prep_warps = NQ + NM;
    prep_kernel<<<(prep_warps * 32 + 255) / 256, 256>>>(q, mem);
    dummy_kernel<<<1, 32>>>(1);
    dummy_kernel<<<1, 32>>>(2);

    dim3 grid(NQ / QT, NCH);
    mma_topk_kernel<<<grid, 512, SMEM_DYN>>>();

    rescore_kernel<<<NQ, 256>>>(mem, out);
}

// round 8
// speedup vs baseline: 1.0766x; 1.0766x over previous
#include <cuda_runtime.h>
#include <cuda_fp8.h>
#include <cstdint>
#include <math.h>

// ---------------- problem constants ----------------
#define NQ     4096
#define NM     100000
#define D      128
#define NCH    37
#define CHUNK  2703          // ceil(NM / NCH)
#define QT     128           // queries per CTA
#define NT     128           // memory rows per tile (64 tensor + 64 dp4a)
#define KC     8             // candidates kept per (query, chunk)

// ---------------- smem layout ----------------
#define AF8_BYTES  (128 * 128)            // fp8 A, swizzled
#define AS8_STRIDE 144
#define AS8_BYTES  (128 * AS8_STRIDE)     // s8 A, padded rows
#define BF8_BYTES  (64 * 128)             // fp8 B half, swizzled
#define BS8_STRIDE 144
#define BS8_BYTES  (64 * BS8_STRIDE)      // s8 B half, padded rows
#define NBUF       3
#define OFF_AF8    0
#define OFF_AS8    (OFF_AF8 + AF8_BYTES)                 // 16384
#define OFF_BF8    (OFF_AS8 + AS8_BYTES)                 // 34816
#define OFF_BS8    (OFF_BF8 + NBUF * BF8_BYTES)          // 59392
#define SMEM_USED  (OFF_BS8 + NBUF * BS8_BYTES)          // 87040
#define SMEM_DYN   (SMEM_USED + 1024)

// ---------------- device scratch ----------------
__device__ float     g_qn[NQ * D];        // normalized queries (fp32)
__device__ uint32_t  g_qf8[NQ * 32];      // normalized queries (e4m3)
__device__ uint32_t  g_qs8[NQ * 32];      // normalized queries (s8 x127)
__device__ uint32_t  g_mf8[NM * 32];      // normalized memory (e4m3)
__device__ uint32_t  g_ms8[NM * 32];      // normalized memory (s8 x127)
__device__ float     g_invm[NM];          // 1/||m||
__device__ int       g_ci[NQ * NCH * KC];
__device__ int       g_dummy;

// ---------------- PTX helpers (family-generic) ----------------
__device__ __forceinline__ uint32_t s2u(const void* p) {
    uint32_t a;
    asm("{ .reg .u64 t; cvta.to.shared.u64 t, %1; cvt.u32.u64 %0, t; }"
        : "=r"(a) : "l"(p));
    return a;
}
__device__ __forceinline__ void cp16(uint32_t dst, const void* src) {
    asm volatile("cp.async.cg.shared.global [%0], [%1], 16;" :: "r"(dst), "l"(src));
}
#define CP_COMMIT() asm volatile("cp.async.commit_group;" ::: "memory")
#define CP_WAIT0()  asm volatile("cp.async.wait_group 0;" ::: "memory")
#define CP_WAIT1()  asm volatile("cp.async.wait_group 1;" ::: "memory")

__device__ __forceinline__ void ldsm_x4(uint32_t addr, uint32_t& r0, uint32_t& r1,
                                        uint32_t& r2, uint32_t& r3) {
    asm volatile("ldmatrix.sync.aligned.m8n8.x4.shared.b16 {%0,%1,%2,%3}, [%4];"
        : "=r"(r0), "=r"(r1), "=r"(r2), "=r"(r3) : "r"(addr));
}
__device__ __forceinline__ void mma16832(float* d, const uint32_t* a, const uint32_t* b) {
    asm volatile("mma.sync.aligned.m16n8k32.row.col.f32.e4m3.e4m3.f32 "
        "{%0,%1,%2,%3}, {%4,%5,%6,%7}, {%8,%9}, {%0,%1,%2,%3};"
        : "+f"(d[0]), "+f"(d[1]), "+f"(d[2]), "+f"(d[3])
        : "r"(a[0]), "r"(a[1]), "r"(a[2]), "r"(a[3]), "r"(b[0]), "r"(b[1]));
}
__device__ __forceinline__ uint32_t sw_off(int row, int c16) {
    return (uint32_t)row * 128u + (uint32_t)((c16 ^ (row & 7)) * 16);
}

// ---------------- top-k inserts ----------------
__device__ __forceinline__ void ins_tb3(float s, int gi,
    float& v0, int& i0, float& v1, int& i1, float& v2, int& i2) {
    bool b2 = (s > v2) || (s == v2 && gi < i2);
    if (!b2) return;
    bool b1 = (s > v1) || (s == v1 && gi < i1);
    if (b1) {
        bool b0 = (s > v0) || (s == v0 && gi < i0);
        if (b0) { v2=v1;i2=i1; v1=v0;i1=i0; v0=s;i0=gi; }
        else    { v2=v1;i2=i1; v1=s;i1=gi; }
    } else      { v2=s; i2=gi; }
}
__device__ __forceinline__ void ins_tb4(float s, int gi,
    float& v0, int& i0, float& v1, int& i1, float& v2, int& i2, float& v3, int& i3) {
    if (!(s > v3)) return;
    if (s > v1) {
        if (s > v0) { v3=v2;i3=i2; v2=v1;i2=i1; v1=v0;i1=i0; v0=s;i0=gi; }
        else        { v3=v2;i3=i2; v2=v1;i2=i1; v1=s;i1=gi; }
    } else {
        if (s > v2) { v3=v2;i3=i2; v2=s;i2=gi; }
        else        { v3=s; i3=gi; }
    }
}

// ---------------- fused prep kernel (normalize, emit fp8 + s8) ----------------
__global__ void prep_kernel(const float* __restrict__ q, const float* __restrict__ m) {
    int w    = (blockIdx.x * blockDim.x + threadIdx.x) >> 5;
    int lane = threadIdx.x & 31;
    if (w < NQ) {
        float4 v = *(const float4*)(q + (size_t)w * D + lane * 4);
        float ss = v.x*v.x + v.y*v.y + v.z*v.z + v.w*v.w;
        #pragma unroll
        for (int o = 16; o; o >>= 1) ss += __shfl_xor_sync(0xffffffffu, ss, o);
        float inv = 1.0f / fmaxf(sqrtf(ss), 1e-12f);
        float4 r = { v.x*inv, v.y*inv, v.z*inv, v.w*inv };
        *(float4*)(g_qn + (size_t)w * D + lane * 4) = r;
        uint32_t lo = __nv_cvt_float2_to_fp8x2(make_float2(r.x, r.y), __NV_SATFINITE, __NV_E4M3);
        uint32_t hi = __nv_cvt_float2_to_fp8x2(make_float2(r.z, r.w), __NV_SATFINITE, __NV_E4M3);
        g_qf8[(size_t)w * 32 + lane] = (lo & 0xffffu) | (hi << 16);
        int a = __float2int_rn(r.x * 127.0f), b = __float2int_rn(r.y * 127.0f);
        int c = __float2int_rn(r.z * 127.0f), d = __float2int_rn(r.w * 127.0f);
        g_qs8[(size_t)w * 32 + lane] =
            (a & 0xff) | ((b & 0xff) << 8) | ((c & 0xff) << 16) | ((d & 0xff) << 24);
    } else if (w < NQ + NM) {
        int row = w - NQ;
        float4 v = *(const float4*)(m + (size_t)row * D + lane * 4);
        float ss = v.x*v.x + v.y*v.y + v.z*v.z + v.w*v.w;
        #pragma unroll
        for (int o = 16; o; o >>= 1) ss += __shfl_xor_sync(0xffffffffu, ss, o);
        float inv = 1.0f / fmaxf(sqrtf(ss), 1e-12f);
        if (lane == 0) g_invm[row] = inv;
        float4 r = { v.x*inv, v.y*inv, v.z*inv, v.w*inv };
        uint32_t lo = __nv_cvt_float2_to_fp8x2(make_float2(r.x, r.y), __NV_SATFINITE, __NV_E4M3);
        uint32_t hi = __nv_cvt_float2_to_fp8x2(make_float2(r.z, r.w), __NV_SATFINITE, __NV_E4M3);
        g_mf8[(size_t)row * 32 + lane] = (lo & 0xffffu) | (hi << 16);
        int a = __float2int_rn(r.x * 127.0f), b = __float2int_rn(r.y * 127.0f);
        int c = __float2int_rn(r.z * 127.0f), d = __float2int_rn(r.w * 127.0f);
        g_ms8[(size_t)row * 32 + lane] =
            (a & 0xff) | ((b & 0xff) << 8) | ((c & 0xff) << 16) | ((d & 0xff) << 24);
    }
}

// ---------------- dummy kernels (keep ncu slot on the main kernel) --------
__global__ void dummy_kernel(int v) { if (threadIdx.x == 1025) g_dummy = v; }

// ---------------- main dual-pipe kernel ----------------
// 512 threads = 16 warps. Warps 0-7: fp8 mma.sync over rows 0..63 of each
// 128-row tile (4M x 2N, warp tile 32x32). Warps 8-15: s8 __dp4a over rows
// 64..127. 2 tensor + 2 dp4a warps per SMSP -> both pipes busy concurrently.
__global__ __launch_bounds__(512, 1) void mma_topk_kernel() {
    extern __shared__ __align__(16) uint8_t dyn[];

    int tid  = threadIdx.x;
    int wid  = tid >> 5;
    int lane = tid & 31;

    uint32_t raw  = s2u(dyn);
    uint32_t base = (raw + 1023u) & ~1023u;
    uint8_t* dbase = (uint8_t*)dyn + (base - raw);
    uint32_t aF8 = base + OFF_AF8;
    uint32_t aS8 = base + OFF_AS8;
    uint32_t bF8 = base + OFF_BF8;
    uint32_t bS8 = base + OFF_BS8;

    int qbase  = blockIdx.x * QT;
    int chunk  = blockIdx.y;
    int mstart = chunk * CHUNK;
    int mend   = min(mstart + CHUNK, NM);
    int T      = (mend - mstart + NT - 1) / NT;

    const char* qf8 = (const char*)g_qf8;
    const char* qs8 = (const char*)g_qs8;
    const char* mf8 = (const char*)g_mf8;
    const char* ms8 = (const char*)g_ms8;

    // B-tile loader geometry: 512 thr -> 2 halves of 256; 64 rows, 4 thr/row
    int lIdx = tid & 255;
    int lRow = lIdx >> 2;            // 0..63
    int lC0  = (lIdx & 3) * 2;
    bool lFp8 = (tid < 256);

    // ---- prologue: A tiles (fp8 swizzled + s8 padded) + B0, B1 ----
    {
        int rowA = tid >> 2;             // 0..127
        int c0 = (tid & 3) * 2;
        #pragma unroll
        for (int j = 0; j < 2; ++j) {
            cp16(aF8 + sw_off(rowA, c0 + j), qf8 + (size_t)(qbase + rowA) * 128 + (c0 + j) * 16);
            cp16(aS8 + rowA * AS8_STRIDE + (c0 + j) * 16,
                 qs8 + (size_t)(qbase + rowA) * 128 + (c0 + j) * 16);
        }
        // B tile 0
        if (lFp8) {
            int gr = min(mstart + lRow, NM - 1);
            #pragma unroll
            for (int j = 0; j < 2; ++j)
                cp16(bF8 + sw_off(lRow, lC0 + j), mf8 + (size_t)gr * 128 + (lC0 + j) * 16);
        } else {
            int gr = min(mstart + 64 + lRow, NM - 1);
            #pragma unroll
            for (int j = 0; j < 2; ++j)
                cp16(bS8 + lRow * BS8_STRIDE + (lC0 + j) * 16,
                     ms8 + (size_t)gr * 128 + (lC0 + j) * 16);
        }
    }
    CP_COMMIT();
    if (T > 1) {    // B tile 1
        if (lFp8) {
            int gr = min(mstart + NT + lRow, NM - 1);
            #pragma unroll
            for (int j = 0; j < 2; ++j)
                cp16(bF8 + BF8_BYTES + sw_off(lRow, lC0 + j), mf8 + (size_t)gr * 128 + (lC0 + j) * 16);
        } else {
            int gr = min(mstart + NT + 64 + lRow, NM - 1);
            #pragma unroll
            for (int j = 0; j < 2; ++j)
                cp16(bS8 + BS8_BYTES + lRow * BS8_STRIDE + (lC0 + j) * 16,
                     ms8 + (size_t)gr * 128 + (lC0 + j) * 16);
        }
        CP_COMMIT();
        CP_WAIT1();
    } else {
        CP_WAIT0();
    }
    __syncthreads();

    // ---------------- per-path state ----------------
    bool isTensor = (wid < 8);
    int wm = wid & 3;                 // tensor: query group (also SMSP id)
    int wn = wid >> 2;                // tensor: 0..1 row half
    int dw = wid - 8;                 // dp4a warp id 0..7
    int qg = dw & 3;                  // dp4a: query group
    int rsel = dw >> 2;               // dp4a: 0..1 row half (of rows 64..127)
    int lg = lane >> 3, ll = lane & 7;

    // tensor: hoist A fragments
    uint32_t afr[4][2][4];
    if (isTensor) {
        int rowA0 = wm * 32 + (lane & 15);
        int hiA = lane >> 4;
        #pragma unroll
        for (int kk = 0; kk < 4; ++kk)
            #pragma unroll
            for (int mt = 0; mt < 2; ++mt)
                ldsm_x4(aF8 + sw_off(rowA0 + mt * 16, 2 * kk + hiA),
                        afr[kk][mt][0], afr[kk][mt][1], afr[kk][mt][2], afr[kk][mt][3]);
    }

    // top-4 lists (both paths use 4 slots, float scores)
    float tv0[4], tv1[4], tv2[4], tv3[4];
    int   ti0[4], ti1[4], ti2[4], ti3[4];
    #pragma unroll
    for (int r = 0; r < 4; ++r) {
        tv0[r]=tv1[r]=tv2[r]=tv3[r] = -2.0f;
        ti0[r]=ti1[r]=ti2[r]=ti3[r] = 0x7fffffff;
    }

    int grp = lane >> 3;
    int rowB0 = wn * 32 + (lane & 7) + (grp >> 1) * 8;   // tensor B ldsm rows
    int hiB = grp & 1;

    const float INV127SQ = 1.0f / 16129.0f;

    for (int t = 0; t < T; ++t) {
        int cur = t % NBUF;
        if (t >= 1 && t + 1 < T) {
            int nb = (t + 1) % NBUF;
            if (lFp8) {
                int gr = min(mstart + (t + 1) * NT + lRow, NM - 1);
                #pragma unroll
                for (int j = 0; j < 2; ++j)
                    cp16(bF8 + nb * BF8_BYTES + sw_off(lRow, lC0 + j),
                         mf8 + (size_t)gr * 128 + (lC0 + j) * 16);
            } else {
                int gr = min(mstart + (t + 1) * NT + 64 + lRow, NM - 1);
                #pragma unroll
                for (int j = 0; j < 2; ++j)
                    cp16(bS8 + nb * BS8_BYTES + lRow * BS8_STRIDE + (lC0 + j) * 16,
                         ms8 + (size_t)gr * 128 + (lC0 + j) * 16);
            }
            CP_COMMIT();
        }
        if (t + 1 < T) CP_WAIT1(); else CP_WAIT0();
        __syncthreads();

        int tb = mstart + t * NT;

        if (isTensor) {
            // ---- fp8 mma over rows tb+0..63 ----
            uint32_t bB = bF8 + cur * BF8_BYTES;
            float acc[2][4][4];
            #pragma unroll
            for (int mt = 0; mt < 2; ++mt)
                #pragma unroll
                for (int nt = 0; nt < 4; ++nt)
                    #pragma unroll
                    for (int e = 0; e < 4; ++e) acc[mt][nt][e] = 0.0f;
            #pragma unroll
            for (int kk = 0; kk < 4; ++kk) {
                uint32_t b[4][2];
                #pragma unroll
                for (int j = 0; j < 2; ++j)
                    ldsm_x4(bB + sw_off(rowB0 + j * 16, 2 * kk + hiB),
                            b[2*j][0], b[2*j][1], b[2*j+1][0], b[2*j+1][1]);
                #pragma unroll
                for (int mt = 0; mt < 2; ++mt)
                    #pragma unroll
                    for (int nt = 0; nt < 4; ++nt)
                        mma16832(acc[mt][nt], afr[kk][mt], b[nt]);
            }
            #pragma unroll
            for (int mt = 0; mt < 2; ++mt)
                #pragma unroll
                for (int h = 0; h < 2; ++h) {
                    const int rs = mt * 2 + h;
                    #pragma unroll
                    for (int nt = 0; nt < 4; ++nt)
                        #pragma unroll
                        for (int c = 0; c < 2; ++c) {
                            float s = acc[mt][nt][h * 2 + c];
                            int gi = tb + wn * 32 + nt * 8 + (lane & 3) * 2 + c;
                            if (gi < mend && s > tv3[rs])
                                ins_tb4(s, gi, tv0[rs],ti0[rs], tv1[rs],ti1[rs],
                                               tv2[rs],ti2[rs], tv3[rs],ti3[rs]);
                        }
                }
        } else {
            // ---- s8 dp4a over rows tb+64..127 ----
            const int4* aq = (const int4*)(dbase + OFF_AS8) + (qg * 32 + ll) * 9;
            const int4* br = (const int4*)(dbase + OFF_BS8 + cur * BS8_BYTES)
                             + (rsel * 32 + lg) * 9;
            int acc[4][8];
            #pragma unroll
            for (int qs = 0; qs < 4; ++qs)
                #pragma unroll
                for (int rr = 0; rr < 8; ++rr) acc[qs][rr] = 0;

            #pragma unroll
            for (int c = 0; c < 8; ++c) {
                int4 qv[4];
                #pragma unroll
                for (int qs = 0; qs < 4; ++qs) qv[qs] = aq[qs * 72 + c];   // 8q*9int4
                #pragma unroll
                for (int h = 0; h < 2; ++h) {
                    int4 rv[4];
                    #pragma unroll
                    for (int k = 0; k < 4; ++k) rv[k] = br[(h * 4 + k) * 36 + c]; // 4rows*9
                    #pragma unroll
                    for (int qs = 0; qs < 4; ++qs)
                        #pragma unroll
                        for (int k = 0; k < 4; ++k) {
                            int a0 = __dp4a(qv[qs].x, rv[k].x, acc[qs][h*4+k]);
                            a0 = __dp4a(qv[qs].y, rv[k].y, a0);
                            a0 = __dp4a(qv[qs].z, rv[k].z, a0);
                            acc[qs][h*4+k] = __dp4a(qv[qs].w, rv[k].w, a0);
                        }
                }
            }
            // epilogue: rows r = rsel*32 + lg + 4*rr (ascending in rr)
            #pragma unroll
            for (int qs = 0; qs < 4; ++qs)
                #pragma unroll
                for (int rr = 0; rr < 8; ++rr) {
                    int gi = tb + 64 + rsel * 32 + lg + 4 * rr;
                    float s = (float)acc[qs][rr] * INV127SQ;
                    if (gi < mend && s > tv3[qs])
                        ins_tb4(s, gi, tv0[qs],ti0[qs], tv1[qs],ti1[qs],
                                       tv2[qs],ti2[qs], tv3[qs],ti3[qs]);
                }
        }
    }

    // ---- lane merges ----
    if (isTensor) {
        #pragma unroll
        for (int off = 1; off <= 2; off <<= 1) {
            #pragma unroll
            for (int rs = 0; rs < 4; ++rs) {
                float ov0 = __shfl_xor_sync(0xffffffffu, tv0[rs], off);
                int   oi0 = __shfl_xor_sync(0xffffffffu, ti0[rs], off);
                float ov1 = __shfl_xor_sync(0xffffffffu, tv1[rs], off);
                int   oi1 = __shfl_xor_sync(0xffffffffu, ti1[rs], off);
                float ov2 = __shfl_xor_sync(0xffffffffu, tv2[rs], off);
                int   oi2 = __shfl_xor_sync(0xffffffffu, ti2[rs], off);
                float ov3 = __shfl_xor_sync(0xffffffffu, tv3[rs], off);
                int   oi3 = __shfl_xor_sync(0xffffffffu, ti3[rs], off);
                ins_tb4(ov0,oi0, tv0[rs],ti0[rs], tv1[rs],ti1[rs], tv2[rs],ti2[rs], tv3[rs],ti3[rs]);
                ins_tb4(ov1,oi1, tv0[rs],ti0[rs], tv1[rs],ti1[rs], tv2[rs],ti2[rs], tv3[rs],ti3[rs]);
                ins_tb4(ov2,oi2, tv0[rs],ti0[rs], tv1[rs],ti1[rs], tv2[rs],ti2[rs], tv3[rs],ti3[rs]);
                ins_tb4(ov3,oi3, tv0[rs],ti0[rs], tv1[rs],ti1[rs], tv2[rs],ti2[rs], tv3[rs],ti3[rs]);
            }
        }
    } else {
        #pragma unroll
        for (int off = 8; off <= 16; off <<= 1) {
            #pragma unroll
            for (int qs = 0; qs < 4; ++qs) {
                float ov0 = __shfl_xor_sync(0xffffffffu, tv0[qs], off);
                int   oi0 = __shfl_xor_sync(0xffffffffu, ti0[qs], off);
                float ov1 = __shfl_xor_sync(0xffffffffu, tv1[qs], off);
                int   oi1 = __shfl_xor_sync(0xffffffffu, ti1[qs], off);
                float ov2 = __shfl_xor_sync(0xffffffffu, tv2[qs], off);
                int   oi2 = __shfl_xor_sync(0xffffffffu, ti2[qs], off);
                float ov3 = __shfl_xor_sync(0xffffffffu, tv3[qs], off);
                int   oi3 = __shfl_xor_sync(0xffffffffu, ti3[qs], off);
                ins_tb4(ov0,oi0, tv0[qs],ti0[qs], tv1[qs],ti1[qs], tv2[qs],ti2[qs], tv3[qs],ti3[qs]);
                ins_tb4(ov1,oi1, tv0[qs],ti0[qs], tv1[qs],ti1[qs], tv2[qs],ti2[qs], tv3[qs],ti3[qs]);
                ins_tb4(ov2,oi2, tv0[qs],ti0[qs], tv1[qs],ti1[qs], tv2[qs],ti2[qs], tv3[qs],ti3[qs]);
                ins_tb4(ov3,oi3, tv0[qs],ti0[qs], tv1[qs],ti1[qs], tv2[qs],ti2[qs], tv3[qs],ti3[qs]);
            }
        }
    }
    __syncthreads();   // all cp.async drained; smem reusable

    // ---- cross-warp merge via smem: [4 segs][128 rows][4 slots] ----
    float* smv = (float*)dbase;                       // 8 KB
    int*   smi = (int*)(dbase + 4 * 128 * 4 * 4);     // 8 KB
    if (isTensor) {
        if ((lane & 3) == 0) {
            #pragma unroll
            for (int rs = 0; rs < 4; ++rs) {
                int row = wm * 32 + (rs >> 1) * 16 + (lane >> 2) + (rs & 1) * 8;
                int o = (wn * 128 + row) * 4;
                smv[o+0]=tv0[rs]; smi[o+0]=ti0[rs];
                smv[o+1]=tv1[rs]; smi[o+1]=ti1[rs];
                smv[o+2]=tv2[rs]; smi[o+2]=ti2[rs];
                smv[o+3]=tv3[rs]; smi[o+3]=ti3[rs];
            }
        }
    } else {
        if (lane < 8) {
            #pragma unroll
            for (int qs = 0; qs < 4; ++qs) {
                int row = qg * 32 + lane + 8 * qs;
                int o = ((2 + rsel) * 128 + row) * 4;
                smv[o+0]=tv0[qs]; smi[o+0]=ti0[qs];
                smv[o+1]=tv1[qs]; smi[o+1]=ti1[qs];
                smv[o+2]=tv2[qs]; smi[o+2]=ti2[qs];
                smv[o+3]=tv3[qs]; smi[o+3]=ti3[qs];
            }
        }
    }
    __syncthreads();
    if (tid < 128) {
        int row = tid;
        float av[16]; int ai[16];
        #pragma unroll
        for (int seg = 0; seg < 4; ++seg)
            #pragma unroll
            for (int j = 0; j < 4; ++j) {
                av[seg*4+j] = smv[(seg * 128 + row) * 4 + j];
                ai[seg*4+j] = smi[(seg * 128 + row) * 4 + j];
            }
        size_t cb = ((size_t)(qbase + row) * NCH + chunk) * KC;
        #pragma unroll
        for (int s = 0; s < KC; ++s) {
            int best = s;
            for (int j = s + 1; j < 16; ++j)
                if (av[j] > av[best]) best = j;
            float bv = av[best]; int bi = ai[best];
            av[best] = av[s]; ai[best] = ai[s];
            av[s] = bv; ai[s] = bi;
            g_ci[cb + s] = bi;
        }
    }
}

// ---------------- exact fp32 rescore + final top-3 ----------------
__global__ void rescore_kernel(const float* __restrict__ mem, float* __restrict__ out) {
    __shared__ float sv[8][3];
    __shared__ int   si[8][3];

    int tid  = threadIdx.x;
    int wid  = tid >> 5;
    int lane = tid & 31;
    int qidx = blockIdx.x;

    float4 qv = *(const float4*)(g_qn + (size_t)qidx * D + lane * 4);

    float v0 = -2.f, v1 = -2.f, v2 = -2.f;
    int   i0 = 0x7fffffff, i1 = 0x7fffffff, i2 = 0x7fffffff;

    size_t cb = (size_t)qidx * NCH * KC;
    #pragma unroll 1
    for (int j = wid; j < NCH * KC; j += 8) {
        int gi = g_ci[cb + j];
        if ((unsigned)gi >= (unsigned)NM) continue;
        float4 mv = *(const float4*)(mem + (size_t)gi * D + lane * 4);
        float s = qv.x*mv.x + qv.y*mv.y + qv.z*mv.z + qv.w*mv.w;
        #pragma unroll
        for (int o = 16; o; o >>= 1) s += __shfl_xor_sync(0xffffffffu, s, o);
        s *= g_invm[gi];
        ins_tb3(s, gi, v0, i0, v1, i1, v2, i2);
    }
    if (lane == 0) {
        sv[wid][0]=v0; si[wid][0]=i0;
        sv[wid][1]=v1; si[wid][1]=i1;
        sv[wid][2]=v2; si[wid][2]=i2;
    }
    __syncthreads();

    if (tid == 0) {
        float w0 = -2.f, w1 = -2.f, w2 = -2.f;
        int   a0 = 0x7fffffff, a1 = 0x7fffffff, a2 = 0x7fffffff;
        #pragma unroll
        for (int p = 0; p < 8; ++p)
            #pragma unroll
            for (int j = 0; j < 3; ++j)
                ins_tb3(sv[p][j], si[p][j], w0,a0, w1,a1, w2,a2);
        out[(size_t)qidx * 3 + 0] = 1.0f - w0;
        out[(size_t)qidx * 3 + 1] = 1.0f - w1;
        out[(size_t)qidx * 3 + 2] = 1.0f - w2;
        out[(size_t)NQ * 3 + (size_t)qidx * 3 + 0] = (float)a0;
        out[(size_t)NQ * 3 + (size_t)qidx * 3 + 1] = (float)a1;
        out[(size_t)NQ * 3 + (size_t)qidx * 3 + 2] = (float)a2;
    }
}

// ---------------- launch ----------------
extern "C" void kernel_launch(void* const* d_in, const int* in_sizes, int n_in,
                              void* d_out, int out_size) {
    const float* q   = (const float*)d_in[0];
    const float* mem = (const float*)d_in[1];
    float* out = (float*)d_out;

    cudaFuncSetAttribute(mma_topk_kernel,
                         cudaFuncAttributeMaxDynamicSharedMemorySize, SMEM_DYN);

    int prep_warps = NQ + NM;
    prep_kernel<<<(prep_warps * 32 + 255) / 256, 256>>>(q, mem);
    dummy_kernel<<<1, 32>>>(1);
    dummy_kernel<<<1, 32>>>(2);

    dim3 grid(NQ / QT, NCH);
    mma_topk_kernel<<<grid, 512, SMEM_DYN>>>();

    rescore_kernel<<<NQ, 256>>>(mem, out);
}